// round 15
// baseline (speedup 1.0000x reference)
#include <cuda_runtime.h>
#include <cuda_bf16.h>
#include <cuda_fp16.h>
#include <math.h>

#define E   320
#define E3  960
#define KQ  128
#define TT  256
#define TM1 255
#define H   10
#define HD  32
#define EPS 1e-5f
#define MAXSPLIT 29        // 10*29=290 blocks <= 296 concurrent -> single wave
#define NKT 20             // K tiles (320/16)
#define TAILB 120          // tail_kernel grid (one block/SM, all co-resident)

typedef unsigned long long u64;
typedef unsigned int u32;

__device__ __forceinline__ u64 pk2(float x, float y) {
    u64 r; asm("mov.b64 %0,{%1,%2};" : "=l"(r) : "f"(x), "f"(y)); return r;
}
__device__ __forceinline__ float2 upk2(u64 a) {
    float2 r; asm("mov.b64 {%0,%1},%2;" : "=f"(r.x), "=f"(r.y) : "l"(a)); return r;
}
__device__ __forceinline__ u64 f2fma(u64 a, u64 b, u64 c) {
    u64 d; asm("fma.rn.f32x2 %0,%1,%2,%3;" : "=l"(d) : "l"(a), "l"(b), "l"(c)); return d;
}
__device__ __forceinline__ u32 pkh(float lo, float hi) {
    u32 r; asm("cvt.rn.f16x2.f32 %0,%1,%2;" : "=r"(r) : "f"(hi), "f"(lo)); return r;
}
__device__ __forceinline__ u32 ex2h2(u32 a) {
    u32 r; asm("ex2.approx.f16x2 %0,%1;" : "=r"(r) : "r"(a)); return r;
}

__device__ __forceinline__ void mma_f16(float* c, u32 a0, u32 a1, u32 a2, u32 a3, u32 b0, u32 b1) {
    asm("mma.sync.aligned.m16n8k16.row.col.f32.f16.f16.f32 "
        "{%0,%1,%2,%3},{%4,%5,%6,%7},{%8,%9},{%0,%1,%2,%3};"
        : "+f"(c[0]), "+f"(c[1]), "+f"(c[2]), "+f"(c[3])
        : "r"(a0), "r"(a1), "r"(a2), "r"(a3), "r"(b0), "r"(b1));
}

__device__ __forceinline__ void cpa8(void* s, const void* g) {
    u32 sa = (u32)__cvta_generic_to_shared(s);
    asm volatile("cp.async.ca.shared.global [%0],[%1],8;" :: "r"(sa), "l"(g));
}

// ---------------- device scratch ----------------
__device__ float g_bf[E3];
__device__ float g_owt[E * E];
__device__ float g_alpha[KQ * E];
__device__ __align__(16) unsigned short g_Qf[H * 8 * 2 * 2 * 32 * 8];
__device__ __align__(16) unsigned short g_Kf[H * 4096 * 2 * 32 * 4];
__device__ __align__(16) unsigned short g_Vf[H * 2048 * 4 * 32 * 4];
__device__ __align__(16) unsigned short g_Af[8 * NKT * 2 * 32 * 8];
__device__ __align__(16) unsigned short g_Wfrag[120 * NKT * 32 * 4];
__device__ float g_pl[MAXSPLIT * H * KQ];
__device__ float g_po[MAXSPLIT * H * KQ * HD];
__device__ unsigned int g_barrier;     // monotonic grid barrier

__device__ __forceinline__ unsigned short h16(float v) {
    __half h = __float2half_rn(v);
    return *(unsigned short*)&h;
}

__device__ __forceinline__ void afrag_store(int row, int e, float v)
{
    int mt = row >> 4, qr = row & 15;
    int kt = e >> 4, dd = e & 15;
    int reg = ((dd >> 3) << 1) | ((qr >> 3) & 1);
    int li = (qr & 7) * 4 + ((dd & 7) >> 1);
    int half = dd & 1;
    int base = (((mt * NKT + kt) * 2 + 0) * 32 + li) * 8 + reg * 2 + half;
    g_Af[base] = h16(v);
}

__device__ __forceinline__ void frag_store(int o, int t, int row, float v)
{
    if (o < E) {
        int hh = o >> 5, d = o & 31;
        int dt = d >> 4, dd = d & 15;
        int reg = ((dd >> 3) << 1), half = dd & 1;
        int q = row;
        int qt = q >> 4, qr = q & 15;
        int rg = reg | ((qr >> 3) & 1);
        int li = (qr & 7) * 4 + ((dd & 7) >> 1);
        int base = ((((hh * 8 + qt) * 2 + dt) * 2 + 0) * 32 + li) * 8 + rg * 2 + half;
        g_Qf[base] = h16(v);
    } else if (o < 2 * E) {
        int e = o - E, hh = e >> 5, d = e & 31;
        int dt = d >> 4, dd = d & 15;
        int reg = dd >> 3, half = dd & 1;
        int key = t * KQ + row;
        int kt = key >> 3, kr = key & 7;
        int li = kr * 4 + ((dd & 7) >> 1);
        int base = (((hh * 4096 + kt) * 2 + dt) * 32 + li) * 4;
        g_Kf[base + reg * 2 + half] = h16(v);
    } else {
        int e = o - 2 * E, hh = e >> 5, d = e & 31;
        int dt = d >> 3, dd = d & 7;
        int key = t * KQ + row;
        int kt = key >> 4, kk = key & 15;
        int reg = kk >> 3, half = kk & 1;
        int li = dd * 4 + ((kk & 7) >> 1);
        int base = (((hh * 2048 + kt) * 4 + dt) * 32 + li) * 4;
        g_Vf[base + reg * 2 + half] = h16(v);
    }
}

// ---------------- one-time: weight fusion -> fp16 B-fragments ----------------
__global__ void fuse_weights(const float* __restrict__ qkvw, const float* __restrict__ qkvb,
                             const float* __restrict__ inw,  const float* __restrict__ inb)
{
    __shared__ float wrow[E];
    int o = blockIdx.x, p = o / E, tid = threadIdx.x;
    wrow[tid] = inw[o * E + tid];
    __syncthreads();
    const float qscale = 0.17677669529663687f * 1.4426950408889634f;  // /sqrt(hd) * log2(e)
    float acc = 0.f;
    int e = tid;
    #pragma unroll 4
    for (int j = 0; j < E; ++j) acc += wrow[j] * qkvw[(p * E + j) * E + e];
    if (p == 0) acc *= qscale;
    {
        int nt = o >> 3, nn = o & 7;
        int kt = e >> 4, dd = e & 15;
        int reg = dd >> 3, half = dd & 1;
        int li = nn * 4 + ((dd & 7) >> 1);
        int base = ((nt * NKT + kt) * 32 + li) * 4;
        g_Wfrag[base + reg * 2 + half] = h16(acc);
    }
    if (tid < 32) {
        float s = 0.f;
        for (int j = tid; j < E; j += 32) s += wrow[j] * qkvb[p * E + j];
        #pragma unroll
        for (int off = 16; off; off >>= 1) s += __shfl_xor_sync(0xffffffffu, s, off);
        if (tid == 0) { float b = s + inb[o]; if (p == 0) b *= qscale; g_bf[o] = b; }
    }
}

__global__ void transpose_ow(const float* __restrict__ outw)
{
    int j = blockIdx.x, i = threadIdx.x;
    g_owt[j * E + i] = outw[i * E + j];
}

// ---------------- initial LayerNorm ----------------
__global__ void init_ln(const float* __restrict__ mu0, const float* __restrict__ lng,
                        const float* __restrict__ lnb, float* __restrict__ out)
{
    __shared__ float red[10];
    __shared__ float mean_s, rstd_s;
    int k = blockIdx.x, tid = threadIdx.x;
    float x = mu0[k * E + tid];
    float s = x;
    #pragma unroll
    for (int off = 16; off; off >>= 1) s += __shfl_xor_sync(0xffffffffu, s, off);
    if ((tid & 31) == 0) red[tid >> 5] = s;
    __syncthreads();
    if (tid == 0) { float m = 0; for (int i = 0; i < 10; ++i) m += red[i]; mean_s = m / E; }
    __syncthreads();
    float d = x - mean_s;
    float v = d * d;
    #pragma unroll
    for (int off = 16; off; off >>= 1) v += __shfl_xor_sync(0xffffffffu, v, off);
    if ((tid & 31) == 0) red[tid >> 5] = v;
    __syncthreads();
    if (tid == 0) { float m = 0; for (int i = 0; i < 10; ++i) m += red[i]; rstd_s = rsqrtf(m / E + EPS); }
    __syncthreads();
    float y = d * rstd_s * lng[tid] + lnb[tid];
    g_alpha[k * E + tid] = y;
    afrag_store(k, tid, y);
    out[k * E + tid] = y;
}

// ---------------- standalone projection (t=0 only) ----------------
__global__ __launch_bounds__(256, 1) void proj_kernel(int t)
{
    __shared__ __align__(16) uint2 sW[NKT * 32];
    int tid = threadIdx.x, w = tid >> 5, lane = tid & 31;
    int nt = blockIdx.x;
    const uint4* Af = (const uint4*)g_Af;
    const uint2* Wf = (const uint2*)g_Wfrag;

    for (int j = tid; j < NKT * 32; j += 256) cpa8(&sW[j], &Wf[nt * NKT * 32 + j]);
    asm volatile("cp.async.commit_group;");

    const uint4* Abase = Af + (w * NKT * 2) * 32 + lane;
    uint4 Ah[NKT];
    #pragma unroll
    for (int k = 0; k < NKT; ++k) Ah[k] = Abase[(2 * k) * 32];

    asm volatile("cp.async.wait_group 0;");
    __syncthreads();

    float C[4] = {0.f, 0.f, 0.f, 0.f};
    #pragma unroll
    for (int k = 0; k < NKT; ++k) {
        uint2 Wv = sW[k * 32 + lane];
        mma_f16(C, Ah[k].x, Ah[k].y, Ah[k].z, Ah[k].w, Wv.x, Wv.y);
    }

    int g = lane >> 2, tig = lane & 3;
    int r0 = w * 16 + g;
    int o0 = nt * 8 + 2 * tig;
    float b0 = g_bf[o0], b1 = g_bf[o0 + 1];
    frag_store(o0,     t, r0,     C[0] + b0);
    frag_store(o0 + 1, t, r0,     C[1] + b1);
    frag_store(o0,     t, r0 + 8, C[2] + b0);
    frag_store(o0 + 1, t, r0 + 8, C[3] + b1);
}

// ---------------- attention: fp16 flash; packed ex2; l via ones-MMA ----------------
__global__ __launch_bounds__(256, 2) void attn_kernel(int t, int nchunk, int split)
{
    __shared__ __align__(16) uint2 sK[2][512];       // 2 x 4KB
    __shared__ __align__(16) uint2 sV[2][512];       // 2 x 4KB
    int tid = threadIdx.x, w = tid >> 5, lane = tid & 31;
    int h = blockIdx.x, sp = blockIdx.y;
    const uint4* Qp = (const uint4*)g_Qf;
    const uint2* Kg = (const uint2*)g_Kf;
    const uint2* Vg = (const uint2*)g_Vf;
    const u32 ONES = 0x3C003C00u;                    // fp16 (1.0, 1.0)

    int qb = ((h * 8 + w) * 2) * 2 * 32;
    uint4 qh0 = Qp[qb + 0 * 32 + lane];
    uint4 qh1 = Qp[qb + 2 * 32 + lane];

    float acc[4][4];
    float lC[4] = {0.f, 0.f, 0.f, 0.f};
    #pragma unroll
    for (int i = 0; i < 4; ++i)
        #pragma unroll
        for (int j = 0; j < 4; ++j) acc[i][j] = 0.f;

    int cA = (sp * nchunk) / split, cB = ((sp + 1) * nchunk) / split;

    {
        const uint2* kg = Kg + (h * 4096 + cA * 8) * 2 * 32;
        const uint2* vg = Vg + (h * 2048 + cA * 4) * 4 * 32;
        cpa8(&sK[0][tid],       &kg[tid]);
        cpa8(&sK[0][tid + 256], &kg[tid + 256]);
        cpa8(&sV[0][tid],       &vg[tid]);
        cpa8(&sV[0][tid + 256], &vg[tid + 256]);
        asm volatile("cp.async.commit_group;");
    }

    int buf = 0;
    for (int c = cA; c < cB; ++c) {
        asm volatile("cp.async.wait_group 0;");
        __syncthreads();
        if (c + 1 < cB) {
            int nb = buf ^ 1;
            const uint2* kg = Kg + (h * 4096 + (c + 1) * 8) * 2 * 32;
            const uint2* vg = Vg + (h * 2048 + (c + 1) * 4) * 4 * 32;
            cpa8(&sK[nb][tid],       &kg[tid]);
            cpa8(&sK[nb][tid + 256], &kg[tid + 256]);
            cpa8(&sV[nb][tid],       &vg[tid]);
            cpa8(&sV[nb][tid + 256], &vg[tid + 256]);
            asm volatile("cp.async.commit_group;");
        }

        float s[8][4];
        #pragma unroll
        for (int i = 0; i < 8; ++i) { s[i][0] = s[i][1] = s[i][2] = s[i][3] = 0.f; }
        #pragma unroll
        for (int i = 0; i < 8; ++i) {
            uint2 kA = sK[buf][(2 * i) * 32 + lane];
            uint2 kB = sK[buf][(2 * i + 1) * 32 + lane];
            mma_f16(s[i], qh0.x, qh0.y, qh0.z, qh0.w, kA.x, kA.y);
            mma_f16(s[i], qh1.x, qh1.y, qh1.z, qh1.w, kB.x, kB.y);
        }

        u32 Pa[8], Pb[8];
        #pragma unroll
        for (int i = 0; i < 8; ++i) {
            Pa[i] = ex2h2(pkh(s[i][0], s[i][1]));
            Pb[i] = ex2h2(pkh(s[i][2], s[i][3]));
        }

        #pragma unroll
        for (int kt = 0; kt < 4; ++kt) {
            u32 pa0 = Pa[2 * kt],     pa1 = Pb[2 * kt];
            u32 pa2 = Pa[2 * kt + 1], pa3 = Pb[2 * kt + 1];
            mma_f16(lC, pa0, pa1, pa2, pa3, ONES, ONES);
            #pragma unroll
            for (int dt = 0; dt < 4; ++dt) {
                uint2 v = sV[buf][(kt * 4 + dt) * 32 + lane];
                mma_f16(acc[dt], pa0, pa1, pa2, pa3, v.x, v.y);
            }
        }
        buf ^= 1;
    }

    int pbase = (sp * H + h) * KQ + w * 16;
    int r0 = lane >> 2, col0 = 2 * (lane & 3);
    #pragma unroll
    for (int dt = 0; dt < 4; ++dt) {
        *(float2*)&g_po[(pbase + r0) * HD + dt * 8 + col0]     = make_float2(acc[dt][0], acc[dt][1]);
        *(float2*)&g_po[(pbase + r0 + 8) * HD + dt * 8 + col0] = make_float2(acc[dt][2], acc[dt][3]);
    }
    if ((lane & 3) == 0) {
        g_pl[pbase + r0]     = lC[0];
        g_pl[pbase + r0 + 8] = lC[2];
    }
}

// ---------------- tail: epilogue(t) [64 blocks] + barrier [120] + proj(t+1) [120] ----------------
__global__ __launch_bounds__(320, 1) void tail_kernel(int tnext, int split, const float* __restrict__ outb,
                                const float* __restrict__ lng, const float* __restrict__ lnb,
                                float* __restrict__ out, int do_proj)
{
    __shared__ float o_sh[2][E];
    __shared__ float res[2][E];
    __shared__ float lcinv[2][H];
    __shared__ float mean2[2], rstd2[2];
    __shared__ __align__(16) uint2 sW[NKT * 32];     // 5KB (one proj n-tile)
    int tid = threadIdx.x;
    int bid = blockIdx.x;

    // ===== phase A: epilogue (blocks 0..63) =====
    if (bid < 64) {
        int k0 = bid * 2;
        if (tid < 2 * H) {
            int r = tid / H, hh = tid % H;
            int row = k0 + r;
            float lsum = 0.f;
            for (int sp = 0; sp < split; ++sp)
                lsum += g_pl[(sp * H + hh) * KQ + row];
            lcinv[r][hh] = 1.f / lsum;
        }
        __syncthreads();

        for (int idx = tid; idx < 2 * E; idx += 320) {
            int r = idx / E, e = idx - r * E;
            int hh = e >> 5, d = e & 31, row = k0 + r;
            float o = 0.f;
            for (int sp = 0; sp < split; ++sp)
                o += g_po[((sp * H + hh) * KQ + row) * HD + d];
            o_sh[r][e] = o * lcinv[r][hh];
        }
        __syncthreads();

        {
            u64 acc = 0ull;
            int i = tid;
            #pragma unroll 8
            for (int j = 0; j < E; ++j) {
                float wv = g_owt[j * E + i];
                acc = f2fma(pk2(o_sh[0][j], o_sh[1][j]), pk2(wv, wv), acc);
            }
            float2 av = upk2(acc);
            float ob = outb[i];
            res[0][i] = av.x + ob + g_alpha[(k0 + 0) * E + i];
            res[1][i] = av.y + ob + g_alpha[(k0 + 1) * E + i];
        }
        __syncthreads();

        {
            int w = tid >> 5, lane = tid & 31;
            if (w < 2) {
                float s = 0.f;
                for (int ii = lane; ii < E; ii += 32) s += res[w][ii];
                #pragma unroll
                for (int off = 16; off; off >>= 1) s += __shfl_xor_sync(0xffffffffu, s, off);
                float mean = s / E;
                float v = 0.f;
                for (int ii = lane; ii < E; ii += 32) { float d2 = res[w][ii] - mean; v += d2 * d2; }
                #pragma unroll
                for (int off = 16; off; off >>= 1) v += __shfl_xor_sync(0xffffffffu, v, off);
                if (lane == 0) { mean2[w] = mean; rstd2[w] = rsqrtf(v / E + EPS); }
            }
        }
        __syncthreads();
        {
            float gg = lng[tid], bb = lnb[tid];
            #pragma unroll
            for (int r = 0; r < 2; ++r) {
                float y = (res[r][tid] - mean2[r]) * rstd2[r] * gg + bb;
                g_alpha[(k0 + r) * E + tid] = y;
                afrag_store(k0 + r, tid, y);
                out[((size_t)tnext * KQ + k0 + r) * E + tid] = y;
            }
        }
        __threadfence();
    }
    __syncthreads();

    // ===== grid barrier (monotonic counter; 120 blocks, all co-resident) =====
    if (tid == 0) {
        unsigned int arrival = atomicAdd(&g_barrier, 1u) + 1u;
        unsigned int target = ((arrival - 1u) / TAILB + 1u) * TAILB;
        while ((int)(*(volatile unsigned int*)&g_barrier - target) < 0) { }
    }
    __syncthreads();
    __threadfence();

    // ===== phase B: proj for step tnext (all 120 blocks, 1 n-tile each) =====
    if (!do_proj) return;
    const uint2* Wf = (const uint2*)g_Wfrag;
    for (int j = tid; j < NKT * 32; j += 320) cpa8(&sW[j], &Wf[bid * NKT * 32 + j]);
    asm volatile("cp.async.commit_group;");

    int w = tid >> 5, lane = tid & 31;
    uint4 Ah[NKT];
    if (w < 8) {
        const uint4* Af = (const uint4*)g_Af;
        const uint4* Abase = Af + (w * NKT * 2) * 32 + lane;
        #pragma unroll
        for (int k = 0; k < NKT; ++k) Ah[k] = Abase[(2 * k) * 32];
    }
    asm volatile("cp.async.wait_group 0;");
    __syncthreads();

    if (w < 8) {
        float C[4] = {0.f, 0.f, 0.f, 0.f};
        #pragma unroll
        for (int k = 0; k < NKT; ++k) {
            uint2 Wv = sW[k * 32 + lane];
            mma_f16(C, Ah[k].x, Ah[k].y, Ah[k].z, Ah[k].w, Wv.x, Wv.y);
        }
        int g = lane >> 2, tig = lane & 3;
        int r0 = w * 16 + g;
        int o0 = bid * 8 + 2 * tig;
        float b0 = g_bf[o0], b1 = g_bf[o0 + 1];
        frag_store(o0,     tnext, r0,     C[0] + b0);
        frag_store(o0 + 1, tnext, r0,     C[1] + b1);
        frag_store(o0,     tnext, r0 + 8, C[2] + b0);
        frag_store(o0 + 1, tnext, r0 + 8, C[3] + b1);
    }
}

// ---------------- host ----------------
extern "C" void kernel_launch(void* const* d_in, const int* in_sizes, int n_in,
                              void* d_out, int out_size)
{
    const float* mu0   = (const float*)d_in[0];
    const float* qkvw  = (const float*)d_in[1];
    const float* qkvb  = (const float*)d_in[2];
    const float* inw   = (const float*)d_in[3];
    const float* inb   = (const float*)d_in[4];
    const float* outw  = (const float*)d_in[5];
    const float* outb  = (const float*)d_in[6];
    const float* lng   = (const float*)d_in[7];
    const float* lnb   = (const float*)d_in[8];
    float* out = (float*)d_out;

    fuse_weights<<<E3, E>>>(qkvw, qkvb, inw, inb);
    transpose_ow<<<E, E>>>(outw);
    init_ln<<<KQ, E>>>(mu0, lng, lnb, out);
    proj_kernel<<<120, 256>>>(0);

    for (int t = 0; t < TM1; ++t) {
        int nchunk = 2 * (t + 1);
        int split = (nchunk < MAXSPLIT) ? nchunk : MAXSPLIT;
        attn_kernel<<<dim3(H, split), 256>>>(t, nchunk, split);
        tail_kernel<<<TAILB, 320>>>(t + 1, split, outb, lng, lnb, out,
                                    (t + 1 < TM1) ? 1 : 0);
    }
}

// round 16
// speedup vs baseline: 1.1018x; 1.1018x over previous
#include <cuda_runtime.h>
#include <cuda_bf16.h>
#include <cuda_fp16.h>
#include <math.h>

#define E   320
#define E3  960
#define KQ  128
#define TT  256
#define TM1 255
#define H   10
#define HD  32
#define EPS 1e-5f
#define MAXSPLIT 29        // 10*29=290 blocks <= 296 concurrent -> single wave
#define NKT 20             // K tiles (320/16)

typedef unsigned long long u64;
typedef unsigned int u32;

__device__ __forceinline__ u64 pk2(float x, float y) {
    u64 r; asm("mov.b64 %0,{%1,%2};" : "=l"(r) : "f"(x), "f"(y)); return r;
}
__device__ __forceinline__ float2 upk2(u64 a) {
    float2 r; asm("mov.b64 {%0,%1},%2;" : "=f"(r.x), "=f"(r.y) : "l"(a)); return r;
}
__device__ __forceinline__ u64 f2fma(u64 a, u64 b, u64 c) {
    u64 d; asm("fma.rn.f32x2 %0,%1,%2,%3;" : "=l"(d) : "l"(a), "l"(b), "l"(c)); return d;
}
__device__ __forceinline__ u32 pkh(float lo, float hi) {
    u32 r; asm("cvt.rn.f16x2.f32 %0,%1,%2;" : "=r"(r) : "f"(hi), "f"(lo)); return r;
}
__device__ __forceinline__ u32 ex2h2(u32 a) {
    u32 r; asm("ex2.approx.f16x2 %0,%1;" : "=r"(r) : "r"(a)); return r;
}

__device__ __forceinline__ void mma_f16(float* c, u32 a0, u32 a1, u32 a2, u32 a3, u32 b0, u32 b1) {
    asm("mma.sync.aligned.m16n8k16.row.col.f32.f16.f16.f32 "
        "{%0,%1,%2,%3},{%4,%5,%6,%7},{%8,%9},{%0,%1,%2,%3};"
        : "+f"(c[0]), "+f"(c[1]), "+f"(c[2]), "+f"(c[3])
        : "r"(a0), "r"(a1), "r"(a2), "r"(a3), "r"(b0), "r"(b1));
}

__device__ __forceinline__ void cpa8(void* s, const void* g) {
    u32 sa = (u32)__cvta_generic_to_shared(s);
    asm volatile("cp.async.ca.shared.global [%0],[%1],8;" :: "r"(sa), "l"(g));
}

// ---------------- device scratch ----------------
__device__ float g_bf[E3];
__device__ float g_owt[E * E];
__device__ float g_alpha[KQ * E];
__device__ __align__(16) unsigned short g_Qf[H * 8 * 2 * 2 * 32 * 8];
__device__ __align__(16) unsigned short g_Kf[H * 4096 * 2 * 32 * 4];
__device__ __align__(16) unsigned short g_Vf[H * 2048 * 4 * 32 * 4];
__device__ __align__(16) unsigned short g_Af[8 * NKT * 2 * 32 * 8];
__device__ __align__(16) unsigned short g_Wfrag[120 * NKT * 32 * 4];
__device__ float g_pl[MAXSPLIT * H * KQ];
__device__ float g_po[MAXSPLIT * H * KQ * HD];

__device__ __forceinline__ unsigned short h16(float v) {
    __half h = __float2half_rn(v);
    return *(unsigned short*)&h;
}

__device__ __forceinline__ void afrag_store(int row, int e, float v)
{
    int mt = row >> 4, qr = row & 15;
    int kt = e >> 4, dd = e & 15;
    int reg = ((dd >> 3) << 1) | ((qr >> 3) & 1);
    int li = (qr & 7) * 4 + ((dd & 7) >> 1);
    int half = dd & 1;
    int base = (((mt * NKT + kt) * 2 + 0) * 32 + li) * 8 + reg * 2 + half;
    g_Af[base] = h16(v);
}

__device__ __forceinline__ void frag_store(int o, int t, int row, float v)
{
    if (o < E) {
        int hh = o >> 5, d = o & 31;
        int dt = d >> 4, dd = d & 15;
        int reg = ((dd >> 3) << 1), half = dd & 1;
        int q = row;
        int qt = q >> 4, qr = q & 15;
        int rg = reg | ((qr >> 3) & 1);
        int li = (qr & 7) * 4 + ((dd & 7) >> 1);
        int base = ((((hh * 8 + qt) * 2 + dt) * 2 + 0) * 32 + li) * 8 + rg * 2 + half;
        g_Qf[base] = h16(v);
    } else if (o < 2 * E) {
        int e = o - E, hh = e >> 5, d = e & 31;
        int dt = d >> 4, dd = d & 15;
        int reg = dd >> 3, half = dd & 1;
        int key = t * KQ + row;
        int kt = key >> 3, kr = key & 7;
        int li = kr * 4 + ((dd & 7) >> 1);
        int base = (((hh * 4096 + kt) * 2 + dt) * 32 + li) * 4;
        g_Kf[base + reg * 2 + half] = h16(v);
    } else {
        int e = o - 2 * E, hh = e >> 5, d = e & 31;
        int dt = d >> 3, dd = d & 7;
        int key = t * KQ + row;
        int kt = key >> 4, kk = key & 15;
        int reg = kk >> 3, half = kk & 1;
        int li = dd * 4 + ((kk & 7) >> 1);
        int base = (((hh * 2048 + kt) * 4 + dt) * 32 + li) * 4;
        g_Vf[base + reg * 2 + half] = h16(v);
    }
}

// ---------------- one-time: weight fusion -> fp16 B-fragments ----------------
__global__ void fuse_weights(const float* __restrict__ qkvw, const float* __restrict__ qkvb,
                             const float* __restrict__ inw,  const float* __restrict__ inb)
{
    __shared__ float wrow[E];
    int o = blockIdx.x, p = o / E, tid = threadIdx.x;
    wrow[tid] = inw[o * E + tid];
    __syncthreads();
    const float qscale = 0.17677669529663687f * 1.4426950408889634f;  // /sqrt(hd) * log2(e)
    float acc = 0.f;
    int e = tid;
    #pragma unroll 4
    for (int j = 0; j < E; ++j) acc += wrow[j] * qkvw[(p * E + j) * E + e];
    if (p == 0) acc *= qscale;
    {
        int nt = o >> 3, nn = o & 7;
        int kt = e >> 4, dd = e & 15;
        int reg = dd >> 3, half = dd & 1;
        int li = nn * 4 + ((dd & 7) >> 1);
        int base = ((nt * NKT + kt) * 32 + li) * 4;
        g_Wfrag[base + reg * 2 + half] = h16(acc);
    }
    if (tid < 32) {
        float s = 0.f;
        for (int j = tid; j < E; j += 32) s += wrow[j] * qkvb[p * E + j];
        #pragma unroll
        for (int off = 16; off; off >>= 1) s += __shfl_xor_sync(0xffffffffu, s, off);
        if (tid == 0) { float b = s + inb[o]; if (p == 0) b *= qscale; g_bf[o] = b; }
    }
}

__global__ void transpose_ow(const float* __restrict__ outw)
{
    int j = blockIdx.x, i = threadIdx.x;
    g_owt[j * E + i] = outw[i * E + j];
}

// ---------------- initial LayerNorm ----------------
__global__ void init_ln(const float* __restrict__ mu0, const float* __restrict__ lng,
                        const float* __restrict__ lnb, float* __restrict__ out)
{
    __shared__ float red[10];
    __shared__ float mean_s, rstd_s;
    int k = blockIdx.x, tid = threadIdx.x;
    float x = mu0[k * E + tid];
    float s = x;
    #pragma unroll
    for (int off = 16; off; off >>= 1) s += __shfl_xor_sync(0xffffffffu, s, off);
    if ((tid & 31) == 0) red[tid >> 5] = s;
    __syncthreads();
    if (tid == 0) { float m = 0; for (int i = 0; i < 10; ++i) m += red[i]; mean_s = m / E; }
    __syncthreads();
    float d = x - mean_s;
    float v = d * d;
    #pragma unroll
    for (int off = 16; off; off >>= 1) v += __shfl_xor_sync(0xffffffffu, v, off);
    if ((tid & 31) == 0) red[tid >> 5] = v;
    __syncthreads();
    if (tid == 0) { float m = 0; for (int i = 0; i < 10; ++i) m += red[i]; rstd_s = rsqrtf(m / E + EPS); }
    __syncthreads();
    float y = d * rstd_s * lng[tid] + lnb[tid];
    g_alpha[k * E + tid] = y;
    afrag_store(k, tid, y);
    out[k * E + tid] = y;
}

// ---------------- per-step projection: 240 blocks x 128 thr (2 blocks/SM overlap) ----------------
__global__ __launch_bounds__(128) void proj_kernel(int t)
{
    __shared__ __align__(16) uint2 sW[NKT * 32];     // 5KB
    int tid = threadIdx.x, w = tid >> 5, lane = tid & 31;
    int nt = blockIdx.x >> 1;            // n-tile 0..119
    int mt = (blockIdx.x & 1) * 4 + w;   // m-tile 0..7
    const uint4* Af = (const uint4*)g_Af;
    const uint2* Wf = (const uint2*)g_Wfrag;

    for (int j = tid; j < NKT * 32; j += 128) cpa8(&sW[j], &Wf[nt * NKT * 32 + j]);
    asm volatile("cp.async.commit_group;");

    const uint4* Abase = Af + (mt * NKT * 2) * 32 + lane;
    uint4 Ah[NKT];
    #pragma unroll
    for (int k = 0; k < NKT; ++k) Ah[k] = Abase[(2 * k) * 32];

    asm volatile("cp.async.wait_group 0;");
    __syncthreads();

    float C[4] = {0.f, 0.f, 0.f, 0.f};
    #pragma unroll
    for (int k = 0; k < NKT; ++k) {
        uint2 Wv = sW[k * 32 + lane];
        mma_f16(C, Ah[k].x, Ah[k].y, Ah[k].z, Ah[k].w, Wv.x, Wv.y);
    }

    int g = lane >> 2, tig = lane & 3;
    int r0 = mt * 16 + g;
    int o0 = nt * 8 + 2 * tig;
    float b0 = g_bf[o0], b1 = g_bf[o0 + 1];
    frag_store(o0,     t, r0,     C[0] + b0);
    frag_store(o0 + 1, t, r0,     C[1] + b1);
    frag_store(o0,     t, r0 + 8, C[2] + b0);
    frag_store(o0 + 1, t, r0 + 8, C[3] + b1);
}

// ---------------- attention: fp16 flash; packed ex2; l via ones-MMA ----------------
__global__ __launch_bounds__(256, 2) void attn_kernel(int t, int nchunk, int split)
{
    __shared__ __align__(16) uint2 sK[2][512];       // 2 x 4KB
    __shared__ __align__(16) uint2 sV[2][512];       // 2 x 4KB
    int tid = threadIdx.x, w = tid >> 5, lane = tid & 31;
    int h = blockIdx.x, sp = blockIdx.y;
    const uint4* Qp = (const uint4*)g_Qf;
    const uint2* Kg = (const uint2*)g_Kf;
    const uint2* Vg = (const uint2*)g_Vf;
    const u32 ONES = 0x3C003C00u;                    // fp16 (1.0, 1.0)

    int qb = ((h * 8 + w) * 2) * 2 * 32;
    uint4 qh0 = Qp[qb + 0 * 32 + lane];
    uint4 qh1 = Qp[qb + 2 * 32 + lane];

    float acc[4][4];
    float lC[4] = {0.f, 0.f, 0.f, 0.f};
    #pragma unroll
    for (int i = 0; i < 4; ++i)
        #pragma unroll
        for (int j = 0; j < 4; ++j) acc[i][j] = 0.f;

    int cA = (sp * nchunk) / split, cB = ((sp + 1) * nchunk) / split;

    {
        const uint2* kg = Kg + (h * 4096 + cA * 8) * 2 * 32;
        const uint2* vg = Vg + (h * 2048 + cA * 4) * 4 * 32;
        cpa8(&sK[0][tid],       &kg[tid]);
        cpa8(&sK[0][tid + 256], &kg[tid + 256]);
        cpa8(&sV[0][tid],       &vg[tid]);
        cpa8(&sV[0][tid + 256], &vg[tid + 256]);
        asm volatile("cp.async.commit_group;");
    }

    int buf = 0;
    for (int c = cA; c < cB; ++c) {
        asm volatile("cp.async.wait_group 0;");
        __syncthreads();
        if (c + 1 < cB) {
            int nb = buf ^ 1;
            const uint2* kg = Kg + (h * 4096 + (c + 1) * 8) * 2 * 32;
            const uint2* vg = Vg + (h * 2048 + (c + 1) * 4) * 4 * 32;
            cpa8(&sK[nb][tid],       &kg[tid]);
            cpa8(&sK[nb][tid + 256], &kg[tid + 256]);
            cpa8(&sV[nb][tid],       &vg[tid]);
            cpa8(&sV[nb][tid + 256], &vg[tid + 256]);
            asm volatile("cp.async.commit_group;");
        }

        float s[8][4];
        #pragma unroll
        for (int i = 0; i < 8; ++i) { s[i][0] = s[i][1] = s[i][2] = s[i][3] = 0.f; }
        #pragma unroll
        for (int i = 0; i < 8; ++i) {
            uint2 kA = sK[buf][(2 * i) * 32 + lane];
            uint2 kB = sK[buf][(2 * i + 1) * 32 + lane];
            mma_f16(s[i], qh0.x, qh0.y, qh0.z, qh0.w, kA.x, kA.y);
            mma_f16(s[i], qh1.x, qh1.y, qh1.z, qh1.w, kB.x, kB.y);
        }

        u32 Pa[8], Pb[8];
        #pragma unroll
        for (int i = 0; i < 8; ++i) {
            Pa[i] = ex2h2(pkh(s[i][0], s[i][1]));
            Pb[i] = ex2h2(pkh(s[i][2], s[i][3]));
        }

        #pragma unroll
        for (int kt = 0; kt < 4; ++kt) {
            u32 pa0 = Pa[2 * kt],     pa1 = Pb[2 * kt];
            u32 pa2 = Pa[2 * kt + 1], pa3 = Pb[2 * kt + 1];
            mma_f16(lC, pa0, pa1, pa2, pa3, ONES, ONES);
            #pragma unroll
            for (int dt = 0; dt < 4; ++dt) {
                uint2 v = sV[buf][(kt * 4 + dt) * 32 + lane];
                mma_f16(acc[dt], pa0, pa1, pa2, pa3, v.x, v.y);
            }
        }
        buf ^= 1;
    }

    int pbase = (sp * H + h) * KQ + w * 16;
    int r0 = lane >> 2, col0 = 2 * (lane & 3);
    #pragma unroll
    for (int dt = 0; dt < 4; ++dt) {
        *(float2*)&g_po[(pbase + r0) * HD + dt * 8 + col0]     = make_float2(acc[dt][0], acc[dt][1]);
        *(float2*)&g_po[(pbase + r0 + 8) * HD + dt * 8 + col0] = make_float2(acc[dt][2], acc[dt][3]);
    }
    if ((lane & 3) == 0) {
        g_pl[pbase + r0]     = lC[0];
        g_pl[pbase + r0 + 8] = lC[2];
    }
}

// ---------------- epilogue: MLP-parallel combine + out-proj + residual + LN ----------------
__global__ __launch_bounds__(320, 1) void epilogue_kernel(int t, int split, const float* __restrict__ outb,
                                const float* __restrict__ lng, const float* __restrict__ lnb,
                                float* __restrict__ out)
{
    __shared__ float o_sh[2][E];
    __shared__ float res[2][E];
    __shared__ float lpart[16][20];
    __shared__ float lcinv[2][H];
    __shared__ float mean2[2], rstd2[2];
    int tid = threadIdx.x;
    int k0 = blockIdx.x * 2;

    // --- po combine: 8 independent load chains per thread (4 sp-unroll x 2 rows) ---
    int e = tid;                    // 0..319
    int hh = e >> 5, d = e & 31;
    float a[4] = {0.f, 0.f, 0.f, 0.f}, b[4] = {0.f, 0.f, 0.f, 0.f};
    {
        const float* base0 = &g_po[((hh) * KQ + k0) * HD + d];
        const float* base1 = base0 + HD;          // row k0+1
        const int spstride = H * KQ * HD;
        int sp = 0;
        for (; sp + 4 <= split; sp += 4) {
            #pragma unroll
            for (int u = 0; u < 4; ++u) {
                a[u] += base0[(sp + u) * spstride];
                b[u] += base1[(sp + u) * spstride];
            }
        }
        for (; sp < split; ++sp) {
            a[0] += base0[sp * spstride];
            b[0] += base1[sp * spstride];
        }
    }

    // --- lcinv: parallel over 320 threads ---
    {
        int j20 = tid % 20, g16 = tid / 20;       // g16 in 0..15
        int r = j20 / 10, hhh = j20 % 10;
        int row = k0 + r;
        float ls = 0.f;
        for (int sp = g16; sp < split; sp += 16)
            ls += g_pl[(sp * H + hhh) * KQ + row];
        lpart[g16][j20] = ls;
    }
    __syncthreads();
    if (tid < 20) {
        float s = 0.f;
        #pragma unroll
        for (int g = 0; g < 16; ++g) s += lpart[g][tid];
        lcinv[tid / 10][tid % 10] = 1.f / s;
    }
    __syncthreads();

    o_sh[0][e] = ((a[0] + a[1]) + (a[2] + a[3])) * lcinv[0][hh];
    o_sh[1][e] = ((b[0] + b[1]) + (b[2] + b[3])) * lcinv[1][hh];
    __syncthreads();

    u64 acc = 0ull;
    int i = tid;
    #pragma unroll 8
    for (int j = 0; j < E; ++j) {
        float wv = g_owt[j * E + i];
        acc = f2fma(pk2(o_sh[0][j], o_sh[1][j]), pk2(wv, wv), acc);
    }
    float2 av = upk2(acc);
    float ob = outb[i];
    res[0][i] = av.x + ob + g_alpha[(k0 + 0) * E + i];
    res[1][i] = av.y + ob + g_alpha[(k0 + 1) * E + i];
    __syncthreads();

    int w = tid >> 5, lane = tid & 31;
    if (w < 2) {
        float s = 0.f;
        for (int ii = lane; ii < E; ii += 32) s += res[w][ii];
        #pragma unroll
        for (int off = 16; off; off >>= 1) s += __shfl_xor_sync(0xffffffffu, s, off);
        float mean = s / E;
        float v = 0.f;
        for (int ii = lane; ii < E; ii += 32) { float d2 = res[w][ii] - mean; v += d2 * d2; }
        #pragma unroll
        for (int off = 16; off; off >>= 1) v += __shfl_xor_sync(0xffffffffu, v, off);
        if (lane == 0) { mean2[w] = mean; rstd2[w] = rsqrtf(v / E + EPS); }
    }
    __syncthreads();
    float gg = lng[tid], bb = lnb[tid];
    #pragma unroll
    for (int r = 0; r < 2; ++r) {
        float y = (res[r][tid] - mean2[r]) * rstd2[r] * gg + bb;
        g_alpha[(k0 + r) * E + tid] = y;
        afrag_store(k0 + r, tid, y);
        out[((size_t)(t + 1) * KQ + k0 + r) * E + tid] = y;
    }
}

// ---------------- host ----------------
extern "C" void kernel_launch(void* const* d_in, const int* in_sizes, int n_in,
                              void* d_out, int out_size)
{
    const float* mu0   = (const float*)d_in[0];
    const float* qkvw  = (const float*)d_in[1];
    const float* qkvb  = (const float*)d_in[2];
    const float* inw   = (const float*)d_in[3];
    const float* inb   = (const float*)d_in[4];
    const float* outw  = (const float*)d_in[5];
    const float* outb  = (const float*)d_in[6];
    const float* lng   = (const float*)d_in[7];
    const float* lnb   = (const float*)d_in[8];
    float* out = (float*)d_out;

    fuse_weights<<<E3, E>>>(qkvw, qkvb, inw, inb);
    transpose_ow<<<E, E>>>(outw);
    init_ln<<<KQ, E>>>(mu0, lng, lnb, out);

    for (int t = 0; t < TM1; ++t) {
        proj_kernel<<<240, 128>>>(t);
        int nchunk = 2 * (t + 1);
        int split = (nchunk < MAXSPLIT) ? nchunk : MAXSPLIT;
        attn_kernel<<<dim3(H, split), 256>>>(t, nchunk, split);
        epilogue_kernel<<<KQ / 2, 320>>>(t, split, outb, lng, lnb, out);
    }
}

// round 17
// speedup vs baseline: 1.1057x; 1.0036x over previous
#include <cuda_runtime.h>
#include <cuda_bf16.h>
#include <cuda_fp16.h>
#include <math.h>

#define E   320
#define E3  960
#define KQ  128
#define TT  256
#define TM1 255
#define H   10
#define HD  32
#define EPS 1e-5f
#define MAXSPLIT 29        // 10*29=290 blocks <= 296 concurrent -> single wave
#define NKT 20             // K tiles (320/16)

typedef unsigned long long u64;
typedef unsigned int u32;

__device__ __forceinline__ u64 pk2(float x, float y) {
    u64 r; asm("mov.b64 %0,{%1,%2};" : "=l"(r) : "f"(x), "f"(y)); return r;
}
__device__ __forceinline__ float2 upk2(u64 a) {
    float2 r; asm("mov.b64 {%0,%1},%2;" : "=f"(r.x), "=f"(r.y) : "l"(a)); return r;
}
__device__ __forceinline__ u64 f2fma(u64 a, u64 b, u64 c) {
    u64 d; asm("fma.rn.f32x2 %0,%1,%2,%3;" : "=l"(d) : "l"(a), "l"(b), "l"(c)); return d;
}
__device__ __forceinline__ u32 pkh(float lo, float hi) {
    u32 r; asm("cvt.rn.f16x2.f32 %0,%1,%2;" : "=r"(r) : "f"(hi), "f"(lo)); return r;
}
__device__ __forceinline__ u32 ex2h2(u32 a) {
    u32 r; asm("ex2.approx.f16x2 %0,%1;" : "=r"(r) : "r"(a)); return r;
}

__device__ __forceinline__ void mma_f16(float* c, u32 a0, u32 a1, u32 a2, u32 a3, u32 b0, u32 b1) {
    asm("mma.sync.aligned.m16n8k16.row.col.f32.f16.f16.f32 "
        "{%0,%1,%2,%3},{%4,%5,%6,%7},{%8,%9},{%0,%1,%2,%3};"
        : "+f"(c[0]), "+f"(c[1]), "+f"(c[2]), "+f"(c[3])
        : "r"(a0), "r"(a1), "r"(a2), "r"(a3), "r"(b0), "r"(b1));
}

__device__ __forceinline__ void cpa8(void* s, const void* g) {
    u32 sa = (u32)__cvta_generic_to_shared(s);
    asm volatile("cp.async.ca.shared.global [%0],[%1],8;" :: "r"(sa), "l"(g));
}

// ---------------- device scratch ----------------
__device__ float g_bf[E3];
__device__ float g_owt[E * E];
__device__ float g_alpha[KQ * E];
__device__ __align__(16) unsigned short g_Qf[H * 8 * 2 * 2 * 32 * 8];
__device__ __align__(16) unsigned short g_Kf[H * 4096 * 2 * 32 * 4];
__device__ __align__(16) unsigned short g_Vf[H * 2048 * 4 * 32 * 4];
__device__ __align__(16) unsigned short g_Af[8 * NKT * 2 * 32 * 8];
__device__ __align__(16) unsigned short g_Wfrag[120 * NKT * 32 * 4];
__device__ float g_pl[MAXSPLIT * H * KQ];
__device__ float g_po[MAXSPLIT * H * KQ * HD];

__device__ __forceinline__ unsigned short h16(float v) {
    __half h = __float2half_rn(v);
    return *(unsigned short*)&h;
}

__device__ __forceinline__ void afrag_store(int row, int e, float v)
{
    int mt = row >> 4, qr = row & 15;
    int kt = e >> 4, dd = e & 15;
    int reg = ((dd >> 3) << 1) | ((qr >> 3) & 1);
    int li = (qr & 7) * 4 + ((dd & 7) >> 1);
    int half = dd & 1;
    int base = (((mt * NKT + kt) * 2 + 0) * 32 + li) * 8 + reg * 2 + half;
    g_Af[base] = h16(v);
}

__device__ __forceinline__ void frag_store(int o, int t, int row, float v)
{
    if (o < E) {
        int hh = o >> 5, d = o & 31;
        int dt = d >> 4, dd = d & 15;
        int reg = ((dd >> 3) << 1), half = dd & 1;
        int q = row;
        int qt = q >> 4, qr = q & 15;
        int rg = reg | ((qr >> 3) & 1);
        int li = (qr & 7) * 4 + ((dd & 7) >> 1);
        int base = ((((hh * 8 + qt) * 2 + dt) * 2 + 0) * 32 + li) * 8 + rg * 2 + half;
        g_Qf[base] = h16(v);
    } else if (o < 2 * E) {
        int e = o - E, hh = e >> 5, d = e & 31;
        int dt = d >> 4, dd = d & 15;
        int reg = dd >> 3, half = dd & 1;
        int key = t * KQ + row;
        int kt = key >> 3, kr = key & 7;
        int li = kr * 4 + ((dd & 7) >> 1);
        int base = (((hh * 4096 + kt) * 2 + dt) * 32 + li) * 4;
        g_Kf[base + reg * 2 + half] = h16(v);
    } else {
        int e = o - 2 * E, hh = e >> 5, d = e & 31;
        int dt = d >> 3, dd = d & 7;
        int key = t * KQ + row;
        int kt = key >> 4, kk = key & 15;
        int reg = kk >> 3, half = kk & 1;
        int li = dd * 4 + ((kk & 7) >> 1);
        int base = (((hh * 2048 + kt) * 4 + dt) * 32 + li) * 4;
        g_Vf[base + reg * 2 + half] = h16(v);
    }
}

// ---------------- one-time: weight fusion -> fp16 B-fragments ----------------
__global__ void fuse_weights(const float* __restrict__ qkvw, const float* __restrict__ qkvb,
                             const float* __restrict__ inw,  const float* __restrict__ inb)
{
    __shared__ float wrow[E];
    int o = blockIdx.x, p = o / E, tid = threadIdx.x;
    wrow[tid] = inw[o * E + tid];
    __syncthreads();
    const float qscale = 0.17677669529663687f * 1.4426950408889634f;  // /sqrt(hd) * log2(e)
    float acc = 0.f;
    int e = tid;
    #pragma unroll 4
    for (int j = 0; j < E; ++j) acc += wrow[j] * qkvw[(p * E + j) * E + e];
    if (p == 0) acc *= qscale;
    {
        int nt = o >> 3, nn = o & 7;
        int kt = e >> 4, dd = e & 15;
        int reg = dd >> 3, half = dd & 1;
        int li = nn * 4 + ((dd & 7) >> 1);
        int base = ((nt * NKT + kt) * 32 + li) * 4;
        g_Wfrag[base + reg * 2 + half] = h16(acc);
    }
    if (tid < 32) {
        float s = 0.f;
        for (int j = tid; j < E; j += 32) s += wrow[j] * qkvb[p * E + j];
        #pragma unroll
        for (int off = 16; off; off >>= 1) s += __shfl_xor_sync(0xffffffffu, s, off);
        if (tid == 0) { float b = s + inb[o]; if (p == 0) b *= qscale; g_bf[o] = b; }
    }
}

__global__ void transpose_ow(const float* __restrict__ outw)
{
    int j = blockIdx.x, i = threadIdx.x;
    g_owt[j * E + i] = outw[i * E + j];
}

// ---------------- initial LayerNorm ----------------
__global__ void init_ln(const float* __restrict__ mu0, const float* __restrict__ lng,
                        const float* __restrict__ lnb, float* __restrict__ out)
{
    __shared__ float red[10];
    __shared__ float mean_s, rstd_s;
    int k = blockIdx.x, tid = threadIdx.x;
    float x = mu0[k * E + tid];
    float s = x;
    #pragma unroll
    for (int off = 16; off; off >>= 1) s += __shfl_xor_sync(0xffffffffu, s, off);
    if ((tid & 31) == 0) red[tid >> 5] = s;
    __syncthreads();
    if (tid == 0) { float m = 0; for (int i = 0; i < 10; ++i) m += red[i]; mean_s = m / E; }
    __syncthreads();
    float d = x - mean_s;
    float v = d * d;
    #pragma unroll
    for (int off = 16; off; off >>= 1) v += __shfl_xor_sync(0xffffffffu, v, off);
    if ((tid & 31) == 0) red[tid >> 5] = v;
    __syncthreads();
    if (tid == 0) { float m = 0; for (int i = 0; i < 10; ++i) m += red[i]; rstd_s = rsqrtf(m / E + EPS); }
    __syncthreads();
    float y = d * rstd_s * lng[tid] + lnb[tid];
    g_alpha[k * E + tid] = y;
    afrag_store(k, tid, y);
    out[k * E + tid] = y;
}

// ---------------- per-step projection: 240x128, packed fragment stores ----------------
__global__ __launch_bounds__(128) void proj_kernel(int t)
{
    __shared__ __align__(16) uint2 sW[NKT * 32];     // 5KB
    int tid = threadIdx.x, w = tid >> 5, lane = tid & 31;
    int nt = blockIdx.x >> 1;            // n-tile 0..119
    int mt = (blockIdx.x & 1) * 4 + w;   // m-tile 0..7
    const uint4* Af = (const uint4*)g_Af;
    const uint2* Wf = (const uint2*)g_Wfrag;

    for (int j = tid; j < NKT * 32; j += 128) cpa8(&sW[j], &Wf[nt * NKT * 32 + j]);
    asm volatile("cp.async.commit_group;");

    const uint4* Abase = Af + (mt * NKT * 2) * 32 + lane;
    uint4 Ah[NKT];
    #pragma unroll
    for (int k = 0; k < NKT; ++k) Ah[k] = Abase[(2 * k) * 32];

    asm volatile("cp.async.wait_group 0;");
    __syncthreads();

    float C[4] = {0.f, 0.f, 0.f, 0.f};
    #pragma unroll
    for (int k = 0; k < NKT; ++k) {
        uint2 Wv = sW[k * 32 + lane];
        mma_f16(C, Ah[k].x, Ah[k].y, Ah[k].z, Ah[k].w, Wv.x, Wv.y);
    }

    int g = lane >> 2, tig = lane & 3;
    int r0 = mt * 16 + g;
    int o0 = nt * 8 + 2 * tig;
    float b0 = g_bf[o0], b1 = g_bf[o0 + 1];
    float v00 = C[0] + b0, v01 = C[1] + b1;    // row r0,   cols o0,o0+1
    float v10 = C[2] + b0, v11 = C[3] + b1;    // row r0+8, cols o0,o0+1

    if (nt < 40) {
        // Q: all 4 values contiguous in this thread's 16B lane slot -> one STG.64
        int hh = o0 >> 5, d = o0 & 31;
        int dt = d >> 4, dd = d & 15;                 // dd even
        int regbase = (dd >> 3) << 1;
        int li = g * 4 + ((dd & 7) >> 1);
        int base = (((hh * 8 + mt) * 2 + dt) * 2 * 32 + li) * 8 + regbase * 2;
        uint2 pv; pv.x = pkh(v00, v01); pv.y = pkh(v10, v11);
        *(uint2*)&g_Qf[base] = pv;
    } else if (nt < 80) {
        // K: col pair contiguous per row -> two STG.32 (rows differ in kt)
        int e0 = o0 - E, hh = e0 >> 5, d = e0 & 31;
        int dt = d >> 4, dd = d & 15;                 // dd even
        int reg = dd >> 3;
        int li = g * 4 + ((dd & 7) >> 1);
        int kt0 = t * 16 + mt * 2;                    // key = t*128 + r0; kr = g
        int baseA = (((hh * 4096 + kt0) * 2 + dt) * 32 + li) * 4 + reg * 2;
        int baseB = (((hh * 4096 + kt0 + 1) * 2 + dt) * 32 + li) * 4 + reg * 2;
        *(u32*)&g_Kf[baseA] = pkh(v00, v01);
        *(u32*)&g_Kf[baseB] = pkh(v10, v11);
    } else {
        frag_store(o0,     t, r0,     v00);
        frag_store(o0 + 1, t, r0,     v01);
        frag_store(o0,     t, r0 + 8, v10);
        frag_store(o0 + 1, t, r0 + 8, v11);
    }
}

// ---------------- attention: fp16 flash; packed ex2; l via ones-MMA ----------------
__global__ __launch_bounds__(256, 2) void attn_kernel(int t, int nchunk, int split)
{
    __shared__ __align__(16) uint2 sK[2][512];       // 2 x 4KB
    __shared__ __align__(16) uint2 sV[2][512];       // 2 x 4KB
    int tid = threadIdx.x, w = tid >> 5, lane = tid & 31;
    int h = blockIdx.x, sp = blockIdx.y;
    const uint4* Qp = (const uint4*)g_Qf;
    const uint2* Kg = (const uint2*)g_Kf;
    const uint2* Vg = (const uint2*)g_Vf;
    const u32 ONES = 0x3C003C00u;                    // fp16 (1.0, 1.0)

    int qb = ((h * 8 + w) * 2) * 2 * 32;
    uint4 qh0 = Qp[qb + 0 * 32 + lane];
    uint4 qh1 = Qp[qb + 2 * 32 + lane];

    float acc[4][4];
    float lC[4] = {0.f, 0.f, 0.f, 0.f};
    #pragma unroll
    for (int i = 0; i < 4; ++i)
        #pragma unroll
        for (int j = 0; j < 4; ++j) acc[i][j] = 0.f;

    int cA = (sp * nchunk) / split, cB = ((sp + 1) * nchunk) / split;

    {
        const uint2* kg = Kg + (h * 4096 + cA * 8) * 2 * 32;
        const uint2* vg = Vg + (h * 2048 + cA * 4) * 4 * 32;
        cpa8(&sK[0][tid],       &kg[tid]);
        cpa8(&sK[0][tid + 256], &kg[tid + 256]);
        cpa8(&sV[0][tid],       &vg[tid]);
        cpa8(&sV[0][tid + 256], &vg[tid + 256]);
        asm volatile("cp.async.commit_group;");
    }

    int buf = 0;
    for (int c = cA; c < cB; ++c) {
        asm volatile("cp.async.wait_group 0;");
        __syncthreads();
        if (c + 1 < cB) {
            int nb = buf ^ 1;
            const uint2* kg = Kg + (h * 4096 + (c + 1) * 8) * 2 * 32;
            const uint2* vg = Vg + (h * 2048 + (c + 1) * 4) * 4 * 32;
            cpa8(&sK[nb][tid],       &kg[tid]);
            cpa8(&sK[nb][tid + 256], &kg[tid + 256]);
            cpa8(&sV[nb][tid],       &vg[tid]);
            cpa8(&sV[nb][tid + 256], &vg[tid + 256]);
            asm volatile("cp.async.commit_group;");
        }

        float s[8][4];
        #pragma unroll
        for (int i = 0; i < 8; ++i) { s[i][0] = s[i][1] = s[i][2] = s[i][3] = 0.f; }
        #pragma unroll
        for (int i = 0; i < 8; ++i) {
            uint2 kA = sK[buf][(2 * i) * 32 + lane];
            uint2 kB = sK[buf][(2 * i + 1) * 32 + lane];
            mma_f16(s[i], qh0.x, qh0.y, qh0.z, qh0.w, kA.x, kA.y);
            mma_f16(s[i], qh1.x, qh1.y, qh1.z, qh1.w, kB.x, kB.y);
        }

        u32 Pa[8], Pb[8];
        #pragma unroll
        for (int i = 0; i < 8; ++i) {
            Pa[i] = ex2h2(pkh(s[i][0], s[i][1]));
            Pb[i] = ex2h2(pkh(s[i][2], s[i][3]));
        }

        #pragma unroll
        for (int kt = 0; kt < 4; ++kt) {
            u32 pa0 = Pa[2 * kt],     pa1 = Pb[2 * kt];
            u32 pa2 = Pa[2 * kt + 1], pa3 = Pb[2 * kt + 1];
            mma_f16(lC, pa0, pa1, pa2, pa3, ONES, ONES);
            #pragma unroll
            for (int dt = 0; dt < 4; ++dt) {
                uint2 v = sV[buf][(kt * 4 + dt) * 32 + lane];
                mma_f16(acc[dt], pa0, pa1, pa2, pa3, v.x, v.y);
            }
        }
        buf ^= 1;
    }

    int pbase = (sp * H + h) * KQ + w * 16;
    int r0 = lane >> 2, col0 = 2 * (lane & 3);
    #pragma unroll
    for (int dt = 0; dt < 4; ++dt) {
        *(float2*)&g_po[(pbase + r0) * HD + dt * 8 + col0]     = make_float2(acc[dt][0], acc[dt][1]);
        *(float2*)&g_po[(pbase + r0 + 8) * HD + dt * 8 + col0] = make_float2(acc[dt][2], acc[dt][3]);
    }
    if ((lane & 3) == 0) {
        g_pl[pbase + r0]     = lC[0];
        g_pl[pbase + r0 + 8] = lC[2];
    }
}

// ---------------- epilogue: MLP-parallel combine + out-proj + residual + LN ----------------
__global__ __launch_bounds__(320, 1) void epilogue_kernel(int t, int split, const float* __restrict__ outb,
                                const float* __restrict__ lng, const float* __restrict__ lnb,
                                float* __restrict__ out)
{
    __shared__ float o_sh[2][E];
    __shared__ float res[2][E];
    __shared__ float lpart[16][20];
    __shared__ float lcinv[2][H];
    __shared__ float mean2[2], rstd2[2];
    int tid = threadIdx.x;
    int k0 = blockIdx.x * 2;

    int e = tid;
    int hh = e >> 5, d = e & 31;
    float a[4] = {0.f, 0.f, 0.f, 0.f}, b[4] = {0.f, 0.f, 0.f, 0.f};
    {
        const float* base0 = &g_po[((hh) * KQ + k0) * HD + d];
        const float* base1 = base0 + HD;
        const int spstride = H * KQ * HD;
        int sp = 0;
        for (; sp + 4 <= split; sp += 4) {
            #pragma unroll
            for (int u = 0; u < 4; ++u) {
                a[u] += base0[(sp + u) * spstride];
                b[u] += base1[(sp + u) * spstride];
            }
        }
        for (; sp < split; ++sp) {
            a[0] += base0[sp * spstride];
            b[0] += base1[sp * spstride];
        }
    }

    {
        int j20 = tid % 20, g16 = tid / 20;
        int r = j20 / 10, hhh = j20 % 10;
        int row = k0 + r;
        float ls = 0.f;
        for (int sp = g16; sp < split; sp += 16)
            ls += g_pl[(sp * H + hhh) * KQ + row];
        lpart[g16][j20] = ls;
    }
    __syncthreads();
    if (tid < 20) {
        float s = 0.f;
        #pragma unroll
        for (int g = 0; g < 16; ++g) s += lpart[g][tid];
        lcinv[tid / 10][tid % 10] = 1.f / s;
    }
    __syncthreads();

    o_sh[0][e] = ((a[0] + a[1]) + (a[2] + a[3])) * lcinv[0][hh];
    o_sh[1][e] = ((b[0] + b[1]) + (b[2] + b[3])) * lcinv[1][hh];
    __syncthreads();

    u64 acc = 0ull;
    int i = tid;
    #pragma unroll 8
    for (int j = 0; j < E; ++j) {
        float wv = g_owt[j * E + i];
        acc = f2fma(pk2(o_sh[0][j], o_sh[1][j]), pk2(wv, wv), acc);
    }
    float2 av = upk2(acc);
    float ob = outb[i];
    res[0][i] = av.x + ob + g_alpha[(k0 + 0) * E + i];
    res[1][i] = av.y + ob + g_alpha[(k0 + 1) * E + i];
    __syncthreads();

    int w = tid >> 5, lane = tid & 31;
    if (w < 2) {
        float s = 0.f;
        for (int ii = lane; ii < E; ii += 32) s += res[w][ii];
        #pragma unroll
        for (int off = 16; off; off >>= 1) s += __shfl_xor_sync(0xffffffffu, s, off);
        float mean = s / E;
        float v = 0.f;
        for (int ii = lane; ii < E; ii += 32) { float d2 = res[w][ii] - mean; v += d2 * d2; }
        #pragma unroll
        for (int off = 16; off; off >>= 1) v += __shfl_xor_sync(0xffffffffu, v, off);
        if (lane == 0) { mean2[w] = mean; rstd2[w] = rsqrtf(v / E + EPS); }
    }
    __syncthreads();
    float gg = lng[tid], bb = lnb[tid];
    #pragma unroll
    for (int r = 0; r < 2; ++r) {
        float y = (res[r][tid] - mean2[r]) * rstd2[r] * gg + bb;
        g_alpha[(k0 + r) * E + tid] = y;
        afrag_store(k0 + r, tid, y);
        out[((size_t)(t + 1) * KQ + k0 + r) * E + tid] = y;
    }
}

// ---------------- host ----------------
extern "C" void kernel_launch(void* const* d_in, const int* in_sizes, int n_in,
                              void* d_out, int out_size)
{
    const float* mu0   = (const float*)d_in[0];
    const float* qkvw  = (const float*)d_in[1];
    const float* qkvb  = (const float*)d_in[2];
    const float* inw   = (const float*)d_in[3];
    const float* inb   = (const float*)d_in[4];
    const float* outw  = (const float*)d_in[5];
    const float* outb  = (const float*)d_in[6];
    const float* lng   = (const float*)d_in[7];
    const float* lnb   = (const float*)d_in[8];
    float* out = (float*)d_out;

    fuse_weights<<<E3, E>>>(qkvw, qkvb, inw, inb);
    transpose_ow<<<E, E>>>(outw);
    init_ln<<<KQ, E>>>(mu0, lng, lnb, out);

    for (int t = 0; t < TM1; ++t) {
        proj_kernel<<<240, 128>>>(t);
        int nchunk = 2 * (t + 1);
        int split = (nchunk < MAXSPLIT) ? nchunk : MAXSPLIT;
        attn_kernel<<<dim3(H, split), 256>>>(t, nchunk, split);
        epilogue_kernel<<<KQ / 2, 320>>>(t, split, outb, lng, lnb, out);
    }
}